// round 1
// baseline (speedup 1.0000x reference)
#include <cuda_runtime.h>

// BicycleModel: B=65536 vehicles, 256 steps.
// Inputs (metadata order): start_x[B], start_y[B], start_yaw[B], start_speed[B],
//                          accel[B,256], steering[B,256]
// Output: x[B,256], y[B,256], yaw[B,256], speed[B,256] concatenated (4*B*256 floats).

constexpr int  BV        = 65536;
constexpr int  NS        = 256;
constexpr int  NC        = NS / 4;            // 64 float4 chunks per row
constexpr float DT       = 0.05f;
constexpr float MAX_STEER = 0.52359877559829887f;   // 30 deg
constexpr float MAX_SPEED = 100.0f;
constexpr float INV_WB    = 1.0f / 2.7f;

__global__ __launch_bounds__(256)
void bicycle_kernel(const float*  __restrict__ sx,
                    const float*  __restrict__ sy,
                    const float*  __restrict__ syaw,
                    const float*  __restrict__ ssp,
                    const float4* __restrict__ acc,
                    const float4* __restrict__ str,
                    float*        __restrict__ out)
{
    const int b = blockIdx.x * blockDim.x + threadIdx.x;

    float x   = sx[b];
    float y   = sy[b];
    float yaw = syaw[b];
    float sp  = ssp[b];

    const size_t plane = (size_t)BV * NC;          // in float4 units
    float4* ox = reinterpret_cast<float4*>(out) + (size_t)b * NC;
    float4* oy = ox + plane;
    float4* ow = oy + plane;
    float4* os = ow + plane;

    const float4* arow = acc + (size_t)b * NC;
    const float4* srow = str + (size_t)b * NC;

    // One dynamics step: consumes control (A, ST), advances (x, y, yaw, sp).
    // Uses OLD sp/yaw for kinematics exactly like the reference.
#define STEP(A, ST) do {                                                     \
        float fr   = fmaf(0.01f * sp, sp, 0.1f * sp);                        \
        float spn  = fminf(fmaxf(fmaf(DT, (A) - fr, sp), 0.0f), MAX_SPEED);  \
        float sc   = fminf(fmaxf((ST), -MAX_STEER), MAX_STEER);              \
        float angv = sp * __tanf(sc) * INV_WB;                               \
        float sn, cs;                                                        \
        __sincosf(yaw, &sn, &cs);                                            \
        x   = fmaf(sp * cs, DT, x);                                          \
        y   = fmaf(sp * sn, DT, y);                                          \
        yaw = fmaf(angv, DT, yaw);                                           \
        sp  = spn;                                                           \
    } while (0)

    float4 X, Y, W, S;

    // Software-pipelined control loads, distance 2 (covers ~DRAM latency at
    // this low occupancy: ~3.5 warps/SMSP only).
    float4 aA = arow[0], sA = srow[0];   // current chunk
    float4 aB = arow[1], sB = srow[1];   // +1
    float4 aC = arow[2], sC = srow[2];   // +2

    // Output chunk 0: state s=0 (initial) + steps t=0,1,2 (-> s=1,2,3).
    X.x = x; Y.x = y; W.x = yaw; S.x = sp;
    STEP(aA.x, sA.x);  X.y = x; Y.y = y; W.y = yaw; S.y = sp;
    STEP(aA.y, sA.y);  X.z = x; Y.z = y; W.z = yaw; S.z = sp;
    STEP(aA.z, sA.z);  X.w = x; Y.w = y; W.w = yaw; S.w = sp;
    ox[0] = X; oy[0] = Y; ow[0] = W; os[0] = S;

    // Output chunk c: steps t = 4c-1 (old chunk's .w), 4c, 4c+1, 4c+2.
    // Last executed step: t = 4*63+2 = 254; chunk-63 .w control (t=255) unused,
    // matching the reference (last control discarded).
#pragma unroll 2
    for (int c = 1; c < NC; ++c) {
        STEP(aA.w, sA.w);  X.x = x; Y.x = y; W.x = yaw; S.x = sp;

        // rotate pipeline; clamp prefetch index (duplicate load at the tail,
        // stays in-bounds for every row including b = BV-1)
        aA = aB; sA = sB;
        aB = aC; sB = sC;
        int cp = c + 2 < NC ? c + 2 : NC - 1;
        aC = arow[cp]; sC = srow[cp];

        STEP(aA.x, sA.x);  X.y = x; Y.y = y; W.y = yaw; S.y = sp;
        STEP(aA.y, sA.y);  X.z = x; Y.z = y; W.z = yaw; S.z = sp;
        STEP(aA.z, sA.z);  X.w = x; Y.w = y; W.w = yaw; S.w = sp;

        ox[c] = X; oy[c] = Y; ow[c] = W; os[c] = S;
    }
#undef STEP
}

extern "C" void kernel_launch(void* const* d_in, const int* in_sizes, int n_in,
                              void* d_out, int out_size)
{
    (void)in_sizes; (void)n_in; (void)out_size;
    const float*  sx   = (const float*)d_in[0];
    const float*  sy   = (const float*)d_in[1];
    const float*  syaw = (const float*)d_in[2];
    const float*  ssp  = (const float*)d_in[3];
    const float4* acc  = (const float4*)d_in[4];
    const float4* str  = (const float4*)d_in[5];

    bicycle_kernel<<<BV / 256, 256>>>(sx, sy, syaw, ssp, acc, str, (float*)d_out);
}

// round 2
// speedup vs baseline: 2.3701x; 2.3701x over previous
#include <cuda_runtime.h>

// BicycleModel: B=65536 vehicles, 256 steps.
// Inputs: start_x[B], start_y[B], start_yaw[B], start_speed[B],
//         accel[B,256], steering[B,256]
// Output: x[B,256], y[B,256], yaw[B,256], speed[B,256] (4 planes, float32).
//
// Strategy: thread-per-vehicle recurrence, but ALL global memory traffic is
// warp-coalesced through shared-memory transpose staging (the R1 kernel was
// L1tex-wavefront bound: 32 lines touched per LDG/STG due to 1KB lane stride).

constexpr int BV  = 65536;
constexpr int NS  = 256;
constexpr int BLK = 256;          // threads per block = vehicles per block
constexpr int TC  = 16;           // timesteps per chunk
constexpr int PAD = TC + 1;       // smem row pad -> stride 17, conflict-free
constexpr int NCH = NS / TC;      // 16 chunks

constexpr float DT        = 0.05f;
constexpr float MAX_STEER = 0.52359877559829887f;   // 30 deg
constexpr float MAX_SPEED = 100.0f;
constexpr float INV_WB    = 1.0f / 2.7f;

// 6 staging arrays: acc, steer, x, y, yaw, speed
constexpr int SMEM_FLOATS = 6 * BLK * PAD;
constexpr int SMEM_BYTES  = SMEM_FLOATS * 4;        // 104448 B

__global__ __launch_bounds__(BLK)
void bicycle_kernel(const float* __restrict__ sx,
                    const float* __restrict__ sy,
                    const float* __restrict__ syaw,
                    const float* __restrict__ ssp,
                    const float* __restrict__ acc,
                    const float* __restrict__ str,
                    float*       __restrict__ out)
{
    extern __shared__ float smem[];
    float* s_acc = smem;
    float* s_str = s_acc + BLK * PAD;
    float* s_x   = s_str + BLK * PAD;
    float* s_y   = s_x   + BLK * PAD;
    float* s_w   = s_y   + BLK * PAD;
    float* s_v   = s_w   + BLK * PAD;

    const int tid   = threadIdx.x;
    const int vbase = blockIdx.x * BLK;
    const int b     = vbase + tid;

    float x   = sx[b];
    float y   = sy[b];
    float yaw = syaw[b];
    float sp  = ssp[b];

    const unsigned plane = (unsigned)BV * NS;   // 2^24, fits easily in u32

    // Pointers for this thread's private smem rows (compute phase).
    float* pa = s_acc + tid * PAD;
    float* ps = s_str + tid * PAD;
    float* qx = s_x   + tid * PAD;
    float* qy = s_y   + tid * PAD;
    float* qw = s_w   + tid * PAD;
    float* qv = s_v   + tid * PAD;

    for (int c = 0; c < NCH; ++c) {
        const unsigned tbase = (unsigned)c * TC;

        // ---- Phase 1: coalesced load of controls into smem ----
        // f = it*256 + tid; t fastest (16 per vehicle row) -> warp covers
        // 2 rows x 64B contiguous segments (2 wavefronts per instruction).
#pragma unroll
        for (int it = 0; it < TC; ++it) {
            int f = it * BLK + tid;
            int v = f >> 4;            // f / TC
            int t = f & (TC - 1);      // f % TC
            unsigned g = (unsigned)(vbase + v) * NS + tbase + t;
            s_acc[v * PAD + t] = acc[g];
            s_str[v * PAD + t] = str[g];
        }
        __syncthreads();

        // ---- Phase 2: 16 recurrence steps per thread, stage states ----
        // smem lane stride 17 (gcd(17,32)=1) -> conflict-free.
#pragma unroll
        for (int j = 0; j < TC; ++j) {
            qx[j] = x; qy[j] = y; qw[j] = yaw; qv[j] = sp;

            float A  = pa[j];
            float ST = ps[j];

            float fr   = fmaf(0.01f * sp, sp, 0.1f * sp);
            float spn  = fminf(fmaxf(fmaf(DT, A - fr, sp), 0.0f), MAX_SPEED);
            float sc   = fminf(fmaxf(ST, -MAX_STEER), MAX_STEER);
            float angv = sp * __tanf(sc) * INV_WB;
            float sn, cs;
            __sincosf(yaw, &sn, &cs);
            x   = fmaf(sp * cs, DT, x);
            y   = fmaf(sp * sn, DT, y);
            yaw = fmaf(angv, DT, yaw);
            sp  = spn;
        }
        __syncthreads();

        // ---- Phase 3: coalesced store of 4 state planes ----
        // (No trailing sync needed: next chunk's Phase-1 writes s_acc/s_str,
        //  which Phase 2 finished reading before this sync; next Phase 2's
        //  writes to s_x.. are ordered behind next Phase-1's __syncthreads.)
#pragma unroll
        for (int it = 0; it < TC; ++it) {
            int f = it * BLK + tid;
            int v = f >> 4;
            int t = f & (TC - 1);
            unsigned g = (unsigned)(vbase + v) * NS + tbase + t;
            int s = v * PAD + t;
            out[g]             = s_x[s];
            out[plane + g]     = s_y[s];
            out[2 * plane + g] = s_w[s];
            out[3 * plane + g] = s_v[s];
        }
        __syncthreads();
    }
}

extern "C" void kernel_launch(void* const* d_in, const int* in_sizes, int n_in,
                              void* d_out, int out_size)
{
    (void)in_sizes; (void)n_in; (void)out_size;
    const float* sx   = (const float*)d_in[0];
    const float* sy   = (const float*)d_in[1];
    const float* syaw = (const float*)d_in[2];
    const float* ssp  = (const float*)d_in[3];
    const float* acc  = (const float*)d_in[4];
    const float* str  = (const float*)d_in[5];

    cudaFuncSetAttribute(bicycle_kernel,
                         cudaFuncAttributeMaxDynamicSharedMemorySize,
                         SMEM_BYTES);

    bicycle_kernel<<<BV / BLK, BLK, SMEM_BYTES>>>(sx, sy, syaw, ssp, acc, str,
                                                  (float*)d_out);
}

// round 3
// speedup vs baseline: 2.5498x; 1.0758x over previous
#include <cuda_runtime.h>

// BicycleModel: B=65536 vehicles, 256 steps, 4 output planes [B,256] f32.
// R3: 64-thread blocks (8 blocks/SM -> 8 independent barrier domains/SM),
// register-prefetched controls (distance 1 chunk), LDG.128/STG.128 global ops,
// smem transpose staging with stride-17 pad (conflict-free scalar LDS/STS).

constexpr int BV  = 65536;
constexpr int NS  = 256;
constexpr int BLK = 64;           // vehicles (threads) per block
constexpr int TC  = 16;           // timesteps per chunk
constexpr int NCH = NS / TC;      // 16 chunks
constexpr int PAD = TC + 1;       // smem row stride 17 -> conflict-free
constexpr int ARR = BLK * PAD;
constexpr int NF4 = NS / 4;       // 64 float4 per row

constexpr float DT        = 0.05f;
constexpr float MAX_STEER = 0.52359877559829887f;   // 30 deg
constexpr float MAX_SPEED = 100.0f;
constexpr float INV_WB    = 1.0f / 2.7f;

__global__ __launch_bounds__(BLK)
void bicycle_kernel(const float*  __restrict__ sx,
                    const float*  __restrict__ sy,
                    const float*  __restrict__ syaw,
                    const float*  __restrict__ ssp,
                    const float4* __restrict__ acc,
                    const float4* __restrict__ str,
                    float4*       __restrict__ out)
{
    __shared__ float sm[6 * ARR];          // 26112 B -> 8 blocks/SM
    float* s_acc = sm;
    float* s_str = sm + ARR;
    float* s_x   = sm + 2 * ARR;
    float* s_y   = sm + 3 * ARR;
    float* s_w   = sm + 4 * ARR;
    float* s_v   = sm + 5 * ARR;

    const int tid   = threadIdx.x;
    const int vbase = blockIdx.x * BLK;
    const int b     = vbase + tid;

    float x   = sx[b];
    float y   = sy[b];
    float yaw = syaw[b];
    float sp  = ssp[b];

    const unsigned plane4 = (unsigned)BV * NF4;
    const float4* arow = acc + (unsigned)vbase * NF4;
    const float4* srow = str + (unsigned)vbase * NF4;
    float4* ox = out + (unsigned)vbase * NF4;
    float4* oy = ox + plane4;
    float4* ow = oy + plane4;
    float4* ov = ow + plane4;

    float* pa = s_acc + tid * PAD;
    float* ps = s_str + tid * PAD;
    float* qx = s_x   + tid * PAD;
    float* qy = s_y   + tid * PAD;
    float* qw = s_w   + tid * PAD;
    float* qv = s_v   + tid * PAD;

    float4 ra[4], rs[4];

    // ---- Prologue: load + stage controls for chunk 0 ----
#pragma unroll
    for (int it = 0; it < 4; ++it) {
        int f4 = it * BLK + tid;               // coalesced: 8 rows x 64B / warp
        int v  = f4 >> 2, t4 = f4 & 3;
        ra[it] = arow[(unsigned)v * NF4 + t4];
        rs[it] = srow[(unsigned)v * NF4 + t4];
        int o = v * PAD + t4 * 4;
        s_acc[o] = ra[it].x; s_acc[o+1] = ra[it].y; s_acc[o+2] = ra[it].z; s_acc[o+3] = ra[it].w;
        s_str[o] = rs[it].x; s_str[o+1] = rs[it].y; s_str[o+2] = rs[it].z; s_str[o+3] = rs[it].w;
    }
    __syncthreads();

    for (int c = 0; c < NCH; ++c) {
        // ---- Prefetch controls for chunk c+1 into registers (hides DRAM) ----
        if (c + 1 < NCH) {
#pragma unroll
            for (int it = 0; it < 4; ++it) {
                int f4 = it * BLK + tid;
                int v  = f4 >> 2, t4 = f4 & 3;
                unsigned g4 = (unsigned)v * NF4 + (unsigned)(c + 1) * 4 + t4;
                ra[it] = arow[g4];
                rs[it] = srow[g4];
            }
        }

        // ---- Compute 16 steps, stage states in smem (stride-17, no conflicts) ----
#pragma unroll
        for (int j = 0; j < TC; ++j) {
            qx[j] = x; qy[j] = y; qw[j] = yaw; qv[j] = sp;

            float A  = pa[j];
            float ST = ps[j];

            float fr   = fmaf(0.01f * sp, sp, 0.1f * sp);
            float spn  = fminf(fmaxf(fmaf(DT, A - fr, sp), 0.0f), MAX_SPEED);
            float sc   = fminf(fmaxf(ST, -MAX_STEER), MAX_STEER);
            float angv = sp * __tanf(sc) * INV_WB;
            float sn, cs;
            __sincosf(yaw, &sn, &cs);
            x   = fmaf(sp * cs, DT, x);
            y   = fmaf(sp * sn, DT, y);
            yaw = fmaf(angv, DT, yaw);
            sp  = spn;
        }
        __syncthreads();

        // ---- Coalesced STG.128 of 4 state planes + stage next controls ----
#pragma unroll
        for (int it = 0; it < 4; ++it) {
            int f4 = it * BLK + tid;
            int v  = f4 >> 2, t4 = f4 & 3;
            int o  = v * PAD + t4 * 4;
            unsigned g4 = (unsigned)v * NF4 + (unsigned)c * 4 + t4;

            ox[g4] = make_float4(s_x[o], s_x[o+1], s_x[o+2], s_x[o+3]);
            oy[g4] = make_float4(s_y[o], s_y[o+1], s_y[o+2], s_y[o+3]);
            ow[g4] = make_float4(s_w[o], s_w[o+1], s_w[o+2], s_w[o+3]);
            ov[g4] = make_float4(s_v[o], s_v[o+1], s_v[o+2], s_v[o+3]);

            if (c + 1 < NCH) {
                s_acc[o] = ra[it].x; s_acc[o+1] = ra[it].y; s_acc[o+2] = ra[it].z; s_acc[o+3] = ra[it].w;
                s_str[o] = rs[it].x; s_str[o+1] = rs[it].y; s_str[o+2] = rs[it].z; s_str[o+3] = rs[it].w;
            }
        }
        __syncthreads();
    }
}

extern "C" void kernel_launch(void* const* d_in, const int* in_sizes, int n_in,
                              void* d_out, int out_size)
{
    (void)in_sizes; (void)n_in; (void)out_size;
    const float*  sx   = (const float*)d_in[0];
    const float*  sy   = (const float*)d_in[1];
    const float*  syaw = (const float*)d_in[2];
    const float*  ssp  = (const float*)d_in[3];
    const float4* acc  = (const float4*)d_in[4];
    const float4* str  = (const float4*)d_in[5];

    bicycle_kernel<<<BV / BLK, BLK>>>(sx, sy, syaw, ssp, acc, str, (float4*)d_out);
}